// round 16
// baseline (speedup 1.0000x reference)
#include <cuda_runtime.h>
#include <cuda_bf16.h>
#include <cstdint>

// Problem constants (fixed shapes per reference)
#define NN_MAX 50000
#define EE_MAX 800000

// ---------------- scratch (device globals; no runtime allocation) ----------------
__device__ __align__(16) float g_Q1[NN_MAX * 128];
__device__ __align__(16) float g_K1[NN_MAX * 128];
__device__ __align__(16) float g_V1[NN_MAX * 128];
__device__ __align__(16) float g_S1[NN_MAX * 128];
__device__ __align__(16) float g_h [NN_MAX * 128];
__device__ __align__(16) float g_Q2[NN_MAX * 64];
__device__ __align__(16) float g_K2[NN_MAX * 64];
__device__ __align__(16) float g_V2[NN_MAX * 64];
__device__ __align__(16) float g_S2[NN_MAX * 64];

__device__ int g_cnt[NN_MAX];
__device__ int g_rowptr[NN_MAX + 1];
__device__ int g_cur[NN_MAX];
__device__ int g_psrc[EE_MAX];

// ---------------- CSR build ----------------
__global__ void k_zero(int n) {
    int i = blockIdx.x * blockDim.x + threadIdx.x;
    if (i < n) g_cnt[i] = 0;
}

__global__ void k_hist(const int* __restrict__ dst, int e) {
    int i = blockIdx.x * blockDim.x + threadIdx.x;
    if (i < e) atomicAdd(&g_cnt[dst[i]], 1);
}

__global__ __launch_bounds__(1024) void k_scan(int n) {
    int tid = threadIdx.x;
    int CH = (n + 1023) >> 10;
    int base = tid * CH;
    int lim = min(base + CH, n);

    int sum = 0;
    for (int i = base; i < lim; i++) sum += g_cnt[i];

    int lane = tid & 31, wid = tid >> 5;
    int v = sum;
    #pragma unroll
    for (int off = 1; off < 32; off <<= 1) {
        int t = __shfl_up_sync(0xffffffffu, v, off);
        if (lane >= off) v += t;
    }
    __shared__ int wsum[32];
    if (lane == 31) wsum[wid] = v;
    __syncthreads();
    if (wid == 0) {
        int w = wsum[lane];
        #pragma unroll
        for (int off = 1; off < 32; off <<= 1) {
            int t = __shfl_up_sync(0xffffffffu, w, off);
            if (lane >= off) w += t;
        }
        wsum[lane] = w;
    }
    __syncthreads();
    int excl = v - sum + (wid ? wsum[wid - 1] : 0);

    int run = excl;
    for (int i = base; i < lim; i++) {
        int c = g_cnt[i];
        g_rowptr[i] = run;
        g_cur[i] = run;
        run += c;
    }
    if (tid == 1023) g_rowptr[n] = run;
}

__global__ void k_scatter(const int* __restrict__ src, const int* __restrict__ dst, int e) {
    int i = blockIdx.x * blockDim.x + threadIdx.x;
    if (i < e) {
        int d = dst[i];
        int pos = atomicAdd(&g_cur[d], 1);
        g_psrc[pos] = src[i];
    }
}

// ---------------- tensor-core GEMM: (M x 128) @ (128 x Ncols) + bias ----------------
// split-tf32 (3xTF32): x = hi + lo, C = Ah*Bh + Ah*Bl + Al*Bh  (fp32-class accuracy)
// Tile: BM=128, BN=64, BK=16. 256 threads = 8 warps (4 row x 2 col), warp tile 32x32.
// Register-staged prefetch: next-kk LDGs issued before the mma phase so the global
// latency rides under compute.

__device__ __forceinline__ float* sel_out(int s) {
    switch (s) {
        case 0: return g_Q1; case 1: return g_K1; case 2: return g_V1; case 3: return g_S1;
        case 4: return g_Q2; case 5: return g_K2; case 6: return g_V2; default: return g_S2;
    }
}

__device__ __forceinline__ unsigned f2tf(float x) {
    unsigned r;
    asm("cvt.rna.tf32.f32 %0, %1;" : "=r"(r) : "f"(x));
    return r;
}

__device__ __forceinline__ uint2 split_tf32(float x) {
    unsigned hi = f2tf(x);
    float lof = x - __uint_as_float(hi);
    unsigned lo = f2tf(lof);
    return make_uint2(hi, lo);
}

__device__ __forceinline__ void mma1688(float& c0, float& c1, float& c2, float& c3,
                                        unsigned a0, unsigned a1, unsigned a2, unsigned a3,
                                        unsigned b0, unsigned b1) {
    asm volatile("mma.sync.aligned.m16n8k8.row.col.f32.tf32.tf32.f32 "
                 "{%0,%1,%2,%3}, {%4,%5,%6,%7}, {%8,%9}, {%0,%1,%2,%3};"
                 : "+f"(c0), "+f"(c1), "+f"(c2), "+f"(c3)
                 : "r"(a0), "r"(a1), "r"(a2), "r"(a3), "r"(b0), "r"(b1));
}

#define AS_S 20   // uint2 stride per A row -> conflict-free frag loads
#define BS_S 68   // uint2 stride per B k-row

__global__ __launch_bounds__(256) void gemm_tc(const float* __restrict__ Ain,
                                               const float* __restrict__ W0, const float* __restrict__ W1,
                                               const float* __restrict__ W2, const float* __restrict__ W3,
                                               const float* __restrict__ b0p, const float* __restrict__ b1p,
                                               const float* __restrict__ b2p, const float* __restrict__ b3p,
                                               int M, int Ncols, int outBase)
{
    const float* A = Ain ? Ain : g_h;
    int z = blockIdx.z;
    const float* W    = (z == 0) ? W0  : (z == 1) ? W1  : (z == 2) ? W2  : W3;
    const float* bias = (z == 0) ? b0p : (z == 1) ? b1p : (z == 2) ? b2p : b3p;
    float* C = sel_out(outBase + z);

    __shared__ uint2 As[128 * AS_S];  // [row][k0..15] hi/lo interleaved
    __shared__ uint2 Bs[16 * BS_S];   // [k0..15][n0..63]

    int tid  = threadIdx.x;
    int lane = tid & 31;
    int w    = tid >> 5;
    int rowW = (w & 3) * 32;
    int colW = (w >> 2) * 32;
    int g = lane >> 2, t = lane & 3;

    int rowBase = blockIdx.y * 128;
    int colBase = blockIdx.x * 64;

    // fixed per-thread fill coordinates
    int aRow0 = (tid          ) >> 2, aC0 = ((tid      ) & 3) * 4;
    int aRow1 = (tid + 256    ) >> 2, aC1 = ((tid + 256) & 3) * 4;
    int aGr0  = rowBase + aRow0, aGr1 = rowBase + aRow1;
    int bKrow = tid >> 4, bC = (tid & 15) * 4;

    float acc[2][4][4];
    #pragma unroll
    for (int mi = 0; mi < 2; mi++)
        #pragma unroll
        for (int ni = 0; ni < 4; ni++)
            #pragma unroll
            for (int r = 0; r < 4; r++) acc[mi][ni][r] = 0.f;

    // prologue: stage kk=0 loads in registers
    float4 aR0 = make_float4(0.f, 0.f, 0.f, 0.f);
    float4 aR1 = make_float4(0.f, 0.f, 0.f, 0.f);
    if (aGr0 < M) aR0 = *(const float4*)(A + (size_t)aGr0 * 128 + aC0);
    if (aGr1 < M) aR1 = *(const float4*)(A + (size_t)aGr1 * 128 + aC1);
    float4 bR = *(const float4*)(W + (size_t)bKrow * Ncols + colBase + bC);

    for (int kk = 0; kk < 128; kk += 16) {
        // store staged registers to smem (split)
        As[aRow0 * AS_S + aC0 + 0] = split_tf32(aR0.x);
        As[aRow0 * AS_S + aC0 + 1] = split_tf32(aR0.y);
        As[aRow0 * AS_S + aC0 + 2] = split_tf32(aR0.z);
        As[aRow0 * AS_S + aC0 + 3] = split_tf32(aR0.w);
        As[aRow1 * AS_S + aC1 + 0] = split_tf32(aR1.x);
        As[aRow1 * AS_S + aC1 + 1] = split_tf32(aR1.y);
        As[aRow1 * AS_S + aC1 + 2] = split_tf32(aR1.z);
        As[aRow1 * AS_S + aC1 + 3] = split_tf32(aR1.w);
        Bs[bKrow * BS_S + bC + 0] = split_tf32(bR.x);
        Bs[bKrow * BS_S + bC + 1] = split_tf32(bR.y);
        Bs[bKrow * BS_S + bC + 2] = split_tf32(bR.z);
        Bs[bKrow * BS_S + bC + 3] = split_tf32(bR.w);
        __syncthreads();

        // issue next-kk global loads; latency hidden under the mma phase below
        if (kk < 112) {
            int kn = kk + 16;
            if (aGr0 < M) aR0 = *(const float4*)(A + (size_t)aGr0 * 128 + kn + aC0);
            if (aGr1 < M) aR1 = *(const float4*)(A + (size_t)aGr1 * 128 + kn + aC1);
            bR = *(const float4*)(W + (size_t)(kn + bKrow) * Ncols + colBase + bC);
        }

        #pragma unroll
        for (int ks = 0; ks < 2; ks++) {
            int k0 = ks * 8;
            uint2 af[2][4];
            #pragma unroll
            for (int mi = 0; mi < 2; mi++) {
                int r0 = rowW + mi * 16 + g;
                af[mi][0] = As[(r0    ) * AS_S + k0 + t];
                af[mi][1] = As[(r0 + 8) * AS_S + k0 + t];
                af[mi][2] = As[(r0    ) * AS_S + k0 + t + 4];
                af[mi][3] = As[(r0 + 8) * AS_S + k0 + t + 4];
            }
            uint2 bf[4][2];
            #pragma unroll
            for (int ni = 0; ni < 4; ni++) {
                int col = colW + ni * 8 + g;
                bf[ni][0] = Bs[(k0 + t    ) * BS_S + col];
                bf[ni][1] = Bs[(k0 + t + 4) * BS_S + col];
            }
            // 3xTF32 mma: hi*hi + hi*lo + lo*hi
            #pragma unroll
            for (int mi = 0; mi < 2; mi++) {
                #pragma unroll
                for (int ni = 0; ni < 4; ni++) {
                    float* c = acc[mi][ni];
                    mma1688(c[0], c[1], c[2], c[3],
                            af[mi][0].x, af[mi][1].x, af[mi][2].x, af[mi][3].x,
                            bf[ni][0].x, bf[ni][1].x);
                    mma1688(c[0], c[1], c[2], c[3],
                            af[mi][0].x, af[mi][1].x, af[mi][2].x, af[mi][3].x,
                            bf[ni][0].y, bf[ni][1].y);
                    mma1688(c[0], c[1], c[2], c[3],
                            af[mi][0].y, af[mi][1].y, af[mi][2].y, af[mi][3].y,
                            bf[ni][0].x, bf[ni][1].x);
                }
            }
        }
        __syncthreads();
    }

    // epilogue: bias + store (float2 per c-pair)
    #pragma unroll
    for (int ni = 0; ni < 4; ni++) {
        int col = colBase + colW + ni * 8 + 2 * t;
        float bx = bias[col], by = bias[col + 1];
        #pragma unroll
        for (int mi = 0; mi < 2; mi++) {
            int r0 = rowBase + rowW + mi * 16 + g;
            float* c = acc[mi][ni];
            if (r0 < M) {
                float2 o = make_float2(c[0] + bx, c[1] + by);
                *(float2*)(C + (size_t)r0 * Ncols + col) = o;
            }
            if (r0 + 8 < M) {
                float2 o = make_float2(c[2] + bx, c[3] + by);
                *(float2*)(C + (size_t)(r0 + 8) * Ncols + col) = o;
            }
        }
    }
}

// ---------------- layer-1 aggregation: warp per node, online softmax, H=8 D=16 ----------------
__global__ __launch_bounds__(256) void agg1_kernel(int Nn)
{
    int warp = (blockIdx.x * blockDim.x + threadIdx.x) >> 5;
    int lane = threadIdx.x & 31;
    if (warp >= Nn) return;
    int n = warp;

    const float4* Q4 = (const float4*)g_Q1;
    const float4* K4 = (const float4*)g_K1;
    const float4* V4 = (const float4*)g_V1;
    const float4* S4 = (const float4*)g_S1;

    float4 q = Q4[(size_t)n * 32 + lane];   // lane holds dims 4*lane..4*lane+3; head = lane>>2

    int beg = g_rowptr[n];
    int end = g_rowptr[n + 1];

    float m = -1e30f, s = 0.f;
    float4 acc = make_float4(0.f, 0.f, 0.f, 0.f);

    if (beg < end) {
        int src = g_psrc[beg];
        float4 kk = K4[(size_t)src * 32 + lane];
        float4 vv = V4[(size_t)src * 32 + lane];
        for (int e = beg; e < end; e++) {
            int nsrc = (e + 1 < end) ? g_psrc[e + 1] : src;
            float4 nk = K4[(size_t)nsrc * 32 + lane];
            float4 nv = V4[(size_t)nsrc * 32 + lane];

            float d = kk.x * q.x + kk.y * q.y + kk.z * q.z + kk.w * q.w;
            d += __shfl_xor_sync(0xffffffffu, d, 1);
            d += __shfl_xor_sync(0xffffffffu, d, 2);   // reduced within 4-lane head group
            float sc = d * 0.25f;                       // 1/sqrt(16)

            float mn = fmaxf(m, sc);
            float c  = __expf(m - mn);
            float p  = __expf(sc - mn);
            s = s * c + p;
            acc.x = acc.x * c + p * vv.x;
            acc.y = acc.y * c + p * vv.y;
            acc.z = acc.z * c + p * vv.z;
            acc.w = acc.w * c + p * vv.w;
            m = mn;

            kk = nk; vv = nv;
        }
    }

    float inv = 1.f / (s + 1e-16f);
    float4 sk = S4[(size_t)n * 32 + lane];
    float4 o;
    o.x = fmaxf(acc.x * inv + sk.x, 0.f);
    o.y = fmaxf(acc.y * inv + sk.y, 0.f);
    o.z = fmaxf(acc.z * inv + sk.z, 0.f);
    o.w = fmaxf(acc.w * inv + sk.w, 0.f);
    ((float4*)g_h)[(size_t)n * 32 + lane] = o;
}

// ---------------- layer-2 aggregation: warp per node, online softmax, H=1 D=64 ----------------
__global__ __launch_bounds__(256) void agg2_kernel(float* __restrict__ out, int Nn)
{
    int warp = (blockIdx.x * blockDim.x + threadIdx.x) >> 5;
    int lane = threadIdx.x & 31;
    if (warp >= Nn) return;
    int n = warp;

    const float2* Q2 = (const float2*)g_Q2;
    const float2* K2 = (const float2*)g_K2;
    const float2* V2 = (const float2*)g_V2;
    const float2* S2 = (const float2*)g_S2;

    float2 q = Q2[(size_t)n * 32 + lane];   // lane holds dims 2*lane..2*lane+1

    int beg = g_rowptr[n];
    int end = g_rowptr[n + 1];

    float m = -1e30f, s = 0.f;
    float2 acc = make_float2(0.f, 0.f);

    if (beg < end) {
        int src = g_psrc[beg];
        float2 kk = K2[(size_t)src * 32 + lane];
        float2 vv = V2[(size_t)src * 32 + lane];
        for (int e = beg; e < end; e++) {
            int nsrc = (e + 1 < end) ? g_psrc[e + 1] : src;
            float2 nk = K2[(size_t)nsrc * 32 + lane];
            float2 nv = V2[(size_t)nsrc * 32 + lane];

            float d = kk.x * q.x + kk.y * q.y;
            #pragma unroll
            for (int off = 16; off > 0; off >>= 1)
                d += __shfl_xor_sync(0xffffffffu, d, off);
            float sc = d * 0.125f;                      // 1/sqrt(64)

            float mn = fmaxf(m, sc);
            float c  = __expf(m - mn);
            float p  = __expf(sc - mn);
            s = s * c + p;
            acc.x = acc.x * c + p * vv.x;
            acc.y = acc.y * c + p * vv.y;
            m = mn;

            kk = nk; vv = nv;
        }
    }

    float inv = 1.f / (s + 1e-16f);
    float2 sk = S2[(size_t)n * 32 + lane];
    float2 o;
    o.x = acc.x * inv + sk.x;
    o.y = acc.y * inv + sk.y;
    ((float2*)out)[(size_t)n * 32 + lane] = o;
}

// ---------------- launch ----------------
extern "C" void kernel_launch(void* const* d_in, const int* in_sizes, int n_in,
                              void* d_out, int out_size)
{
    const float* x   = (const float*)d_in[0];
    const float* Wq1 = (const float*)d_in[1];  const float* bq1 = (const float*)d_in[2];
    const float* Wk1 = (const float*)d_in[3];  const float* bk1 = (const float*)d_in[4];
    const float* Wv1 = (const float*)d_in[5];  const float* bv1 = (const float*)d_in[6];
    const float* Ws1 = (const float*)d_in[7];  const float* bs1 = (const float*)d_in[8];
    const float* Wq2 = (const float*)d_in[9];  const float* bq2 = (const float*)d_in[10];
    const float* Wk2 = (const float*)d_in[11]; const float* bk2 = (const float*)d_in[12];
    const float* Wv2 = (const float*)d_in[13]; const float* bv2 = (const float*)d_in[14];
    const float* Ws2 = (const float*)d_in[15]; const float* bs2 = (const float*)d_in[16];
    const int* esrc  = (const int*)d_in[17];
    const int* edst  = (const int*)d_in[18];
    float* out = (float*)d_out;

    int Nn = in_sizes[0] / 128;
    int E  = in_sizes[17];

    // One-time side-stream + events (created on the correctness call, which
    // precedes graph capture; reused identically on every call).
    static cudaStream_t s2 = nullptr;
    static cudaEvent_t evFork = nullptr, evJoin = nullptr;
    if (s2 == nullptr) {
        cudaStreamCreateWithFlags(&s2, cudaStreamNonBlocking);
        cudaEventCreateWithFlags(&evFork, cudaEventDisableTiming);
        cudaEventCreateWithFlags(&evJoin, cudaEventDisableTiming);
    }

    // ---- fork: CSR build on s2, concurrent with layer-1 projections ----
    cudaEventRecord(evFork, 0);
    cudaStreamWaitEvent(s2, evFork, 0);

    k_zero<<<(Nn + 255) / 256, 256, 0, s2>>>(Nn);
    k_hist<<<(E + 255) / 256, 256, 0, s2>>>(edst, E);
    k_scan<<<1, 1024, 0, s2>>>(Nn);
    k_scatter<<<(E + 255) / 256, 256, 0, s2>>>(esrc, edst, E);
    cudaEventRecord(evJoin, s2);

    // main stream: layer-1 projections (Q,K,V,S via blockIdx.z)
    dim3 g1(2, (Nn + 127) / 128, 4);
    gemm_tc<<<g1, 256>>>(x, Wq1, Wk1, Wv1, Ws1, bq1, bk1, bv1, bs1, Nn, 128, 0);

    // ---- join: agg1 needs both CSR and projections ----
    cudaStreamWaitEvent(0, evJoin, 0);

    int aggBlocks = (Nn + 7) / 8;   // 8 warps per 256-thread block
    agg1_kernel<<<aggBlocks, 256>>>(Nn);

    // layer-2 projections: [N,128] @ [128,64] + b (A = g_h via nullptr)
    dim3 g2(1, (Nn + 127) / 128, 4);
    gemm_tc<<<g2, 256>>>(nullptr, Wq2, Wk2, Wv2, Ws2, bq2, bk2, bv2, bs2, Nn, 64, 4);

    agg2_kernel<<<aggBlocks, 256>>>(out, Nn);
}

// round 17
// speedup vs baseline: 1.0659x; 1.0659x over previous
#include <cuda_runtime.h>
#include <cuda_bf16.h>
#include <cstdint>

// Problem constants (fixed shapes per reference)
#define NN_MAX 50000
#define EE_MAX 800000

// ---------------- scratch (device globals; no runtime allocation) ----------------
__device__ __align__(16) float g_Q1[NN_MAX * 128];
__device__ __align__(16) float g_K1[NN_MAX * 128];
__device__ __align__(16) float g_V1[NN_MAX * 128];
__device__ __align__(16) float g_S1[NN_MAX * 128];
__device__ __align__(16) float g_h [NN_MAX * 128];
__device__ __align__(16) float g_Q2[NN_MAX * 64];
__device__ __align__(16) float g_K2[NN_MAX * 64];
__device__ __align__(16) float g_V2[NN_MAX * 64];
__device__ __align__(16) float g_S2[NN_MAX * 64];

__device__ int g_cnt[NN_MAX];
__device__ int g_rowptr[NN_MAX + 1];
__device__ int g_cur[NN_MAX];
__device__ int g_psrc[EE_MAX];

// ---------------- CSR build ----------------
__global__ void k_zero(int n) {
    int i = blockIdx.x * blockDim.x + threadIdx.x;
    if (i < n) g_cnt[i] = 0;
}

__global__ void k_hist(const int* __restrict__ dst, int e) {
    int i = blockIdx.x * blockDim.x + threadIdx.x;
    if (i < e) atomicAdd(&g_cnt[dst[i]], 1);
}

__global__ __launch_bounds__(1024) void k_scan(int n) {
    int tid = threadIdx.x;
    int CH = (n + 1023) >> 10;
    int base = tid * CH;
    int lim = min(base + CH, n);

    int sum = 0;
    for (int i = base; i < lim; i++) sum += g_cnt[i];

    int lane = tid & 31, wid = tid >> 5;
    int v = sum;
    #pragma unroll
    for (int off = 1; off < 32; off <<= 1) {
        int t = __shfl_up_sync(0xffffffffu, v, off);
        if (lane >= off) v += t;
    }
    __shared__ int wsum[32];
    if (lane == 31) wsum[wid] = v;
    __syncthreads();
    if (wid == 0) {
        int w = wsum[lane];
        #pragma unroll
        for (int off = 1; off < 32; off <<= 1) {
            int t = __shfl_up_sync(0xffffffffu, w, off);
            if (lane >= off) w += t;
        }
        wsum[lane] = w;
    }
    __syncthreads();
    int excl = v - sum + (wid ? wsum[wid - 1] : 0);

    int run = excl;
    for (int i = base; i < lim; i++) {
        int c = g_cnt[i];
        g_rowptr[i] = run;
        g_cur[i] = run;
        run += c;
    }
    if (tid == 1023) g_rowptr[n] = run;
}

__global__ void k_scatter(const int* __restrict__ src, const int* __restrict__ dst, int e) {
    int i = blockIdx.x * blockDim.x + threadIdx.x;
    if (i < e) {
        int d = dst[i];
        int pos = atomicAdd(&g_cur[d], 1);
        g_psrc[pos] = src[i];
    }
}

// ---------------- tensor-core GEMM (R3 config + row offset): ----------------
// split-tf32 (3xTF32): x = hi + lo, C = Ah*Bh + Ah*Bl + Al*Bh
// Tile: BM=128, BN=64, BK=16. 256 threads = 8 warps (4 row x 2 col), warp tile 32x32.
// Output selector map: 0:Q1 1:S1 2:K1 3:V1 4:Q2 5:K2 6:V2 7:S2

__device__ __forceinline__ float* sel_out(int s) {
    switch (s) {
        case 0: return g_Q1; case 1: return g_S1; case 2: return g_K1; case 3: return g_V1;
        case 4: return g_Q2; case 5: return g_K2; case 6: return g_V2; default: return g_S2;
    }
}

__device__ __forceinline__ unsigned f2tf(float x) {
    unsigned r;
    asm("cvt.rna.tf32.f32 %0, %1;" : "=r"(r) : "f"(x));
    return r;
}

__device__ __forceinline__ uint2 split_tf32(float x) {
    unsigned hi = f2tf(x);
    float lof = x - __uint_as_float(hi);
    unsigned lo = f2tf(lof);
    return make_uint2(hi, lo);
}

__device__ __forceinline__ void mma1688(float& c0, float& c1, float& c2, float& c3,
                                        unsigned a0, unsigned a1, unsigned a2, unsigned a3,
                                        unsigned b0, unsigned b1) {
    asm volatile("mma.sync.aligned.m16n8k8.row.col.f32.tf32.tf32.f32 "
                 "{%0,%1,%2,%3}, {%4,%5,%6,%7}, {%8,%9}, {%0,%1,%2,%3};"
                 : "+f"(c0), "+f"(c1), "+f"(c2), "+f"(c3)
                 : "r"(a0), "r"(a1), "r"(a2), "r"(a3), "r"(b0), "r"(b1));
}

#define AS_S 20
#define BS_S 68

__global__ __launch_bounds__(256) void gemm_tc(const float* __restrict__ Ain,
                                               const float* __restrict__ W0, const float* __restrict__ W1,
                                               const float* __restrict__ W2, const float* __restrict__ W3,
                                               const float* __restrict__ b0p, const float* __restrict__ b1p,
                                               const float* __restrict__ b2p, const float* __restrict__ b3p,
                                               int M, int Ncols, int outBase, int rowBeg)
{
    const float* A = Ain ? Ain : g_h;
    int z = blockIdx.z;
    const float* W    = (z == 0) ? W0  : (z == 1) ? W1  : (z == 2) ? W2  : W3;
    const float* bias = (z == 0) ? b0p : (z == 1) ? b1p : (z == 2) ? b2p : b3p;
    float* C = sel_out(outBase + z);

    __shared__ uint2 As[128 * AS_S];
    __shared__ uint2 Bs[16 * BS_S];

    int tid  = threadIdx.x;
    int lane = tid & 31;
    int w    = tid >> 5;
    int rowW = (w & 3) * 32;
    int colW = (w >> 2) * 32;
    int g = lane >> 2, t = lane & 3;

    int rowBase = rowBeg + blockIdx.y * 128;
    int colBase = blockIdx.x * 64;

    float acc[2][4][4];
    #pragma unroll
    for (int mi = 0; mi < 2; mi++)
        #pragma unroll
        for (int ni = 0; ni < 4; ni++)
            #pragma unroll
            for (int r = 0; r < 4; r++) acc[mi][ni][r] = 0.f;

    for (int kk = 0; kk < 128; kk += 16) {
        #pragma unroll
        for (int i = 0; i < 2; i++) {
            int idx = tid + i * 256;
            int row = idx >> 2;
            int c4  = (idx & 3) * 4;
            int gr  = rowBase + row;
            float4 av = make_float4(0.f, 0.f, 0.f, 0.f);
            if (gr < M) av = *(const float4*)(A + (size_t)gr * 128 + kk + c4);
            As[row * AS_S + c4 + 0] = split_tf32(av.x);
            As[row * AS_S + c4 + 1] = split_tf32(av.y);
            As[row * AS_S + c4 + 2] = split_tf32(av.z);
            As[row * AS_S + c4 + 3] = split_tf32(av.w);
        }
        {
            int idx  = tid;
            int krow = idx >> 4;
            int c4   = (idx & 15) * 4;
            float4 bv = *(const float4*)(W + (size_t)(kk + krow) * Ncols + colBase + c4);
            Bs[krow * BS_S + c4 + 0] = split_tf32(bv.x);
            Bs[krow * BS_S + c4 + 1] = split_tf32(bv.y);
            Bs[krow * BS_S + c4 + 2] = split_tf32(bv.z);
            Bs[krow * BS_S + c4 + 3] = split_tf32(bv.w);
        }
        __syncthreads();

        #pragma unroll
        for (int ks = 0; ks < 2; ks++) {
            int k0 = ks * 8;
            uint2 af[2][4];
            #pragma unroll
            for (int mi = 0; mi < 2; mi++) {
                int r0 = rowW + mi * 16 + g;
                af[mi][0] = As[(r0    ) * AS_S + k0 + t];
                af[mi][1] = As[(r0 + 8) * AS_S + k0 + t];
                af[mi][2] = As[(r0    ) * AS_S + k0 + t + 4];
                af[mi][3] = As[(r0 + 8) * AS_S + k0 + t + 4];
            }
            uint2 bf[4][2];
            #pragma unroll
            for (int ni = 0; ni < 4; ni++) {
                int col = colW + ni * 8 + g;
                bf[ni][0] = Bs[(k0 + t    ) * BS_S + col];
                bf[ni][1] = Bs[(k0 + t + 4) * BS_S + col];
            }
            #pragma unroll
            for (int mi = 0; mi < 2; mi++) {
                #pragma unroll
                for (int ni = 0; ni < 4; ni++) {
                    float* c = acc[mi][ni];
                    mma1688(c[0], c[1], c[2], c[3],
                            af[mi][0].x, af[mi][1].x, af[mi][2].x, af[mi][3].x,
                            bf[ni][0].x, bf[ni][1].x);
                    mma1688(c[0], c[1], c[2], c[3],
                            af[mi][0].x, af[mi][1].x, af[mi][2].x, af[mi][3].x,
                            bf[ni][0].y, bf[ni][1].y);
                    mma1688(c[0], c[1], c[2], c[3],
                            af[mi][0].y, af[mi][1].y, af[mi][2].y, af[mi][3].y,
                            bf[ni][0].x, bf[ni][1].x);
                }
            }
        }
        __syncthreads();
    }

    #pragma unroll
    for (int ni = 0; ni < 4; ni++) {
        int col = colBase + colW + ni * 8 + 2 * t;
        float bx = bias[col], by = bias[col + 1];
        #pragma unroll
        for (int mi = 0; mi < 2; mi++) {
            int r0 = rowBase + rowW + mi * 16 + g;
            float* c = acc[mi][ni];
            if (r0 < M) {
                float2 o = make_float2(c[0] + bx, c[1] + by);
                *(float2*)(C + (size_t)r0 * Ncols + col) = o;
            }
            if (r0 + 8 < M) {
                float2 o = make_float2(c[2] + bx, c[3] + by);
                *(float2*)(C + (size_t)(r0 + 8) * Ncols + col) = o;
            }
        }
    }
}

// ---------------- layer-1 aggregation: warp per node, online softmax, H=8 D=16 ----------------
__global__ __launch_bounds__(256) void agg1_kernel(int nodeBeg, int nodeEnd)
{
    int n = nodeBeg + ((blockIdx.x * blockDim.x + threadIdx.x) >> 5);
    int lane = threadIdx.x & 31;
    if (n >= nodeEnd) return;

    const float4* Q4 = (const float4*)g_Q1;
    const float4* K4 = (const float4*)g_K1;
    const float4* V4 = (const float4*)g_V1;
    const float4* S4 = (const float4*)g_S1;

    float4 q = Q4[(size_t)n * 32 + lane];

    int beg = g_rowptr[n];
    int end = g_rowptr[n + 1];

    float m = -1e30f, s = 0.f;
    float4 acc = make_float4(0.f, 0.f, 0.f, 0.f);

    if (beg < end) {
        int src = g_psrc[beg];
        float4 kk = K4[(size_t)src * 32 + lane];
        float4 vv = V4[(size_t)src * 32 + lane];
        for (int e = beg; e < end; e++) {
            int nsrc = (e + 1 < end) ? g_psrc[e + 1] : src;
            float4 nk = K4[(size_t)nsrc * 32 + lane];
            float4 nv = V4[(size_t)nsrc * 32 + lane];

            float d = kk.x * q.x + kk.y * q.y + kk.z * q.z + kk.w * q.w;
            d += __shfl_xor_sync(0xffffffffu, d, 1);
            d += __shfl_xor_sync(0xffffffffu, d, 2);
            float sc = d * 0.25f;

            float mn = fmaxf(m, sc);
            float c  = __expf(m - mn);
            float p  = __expf(sc - mn);
            s = s * c + p;
            acc.x = acc.x * c + p * vv.x;
            acc.y = acc.y * c + p * vv.y;
            acc.z = acc.z * c + p * vv.z;
            acc.w = acc.w * c + p * vv.w;
            m = mn;

            kk = nk; vv = nv;
        }
    }

    float inv = 1.f / (s + 1e-16f);
    float4 sk = S4[(size_t)n * 32 + lane];
    float4 o;
    o.x = fmaxf(acc.x * inv + sk.x, 0.f);
    o.y = fmaxf(acc.y * inv + sk.y, 0.f);
    o.z = fmaxf(acc.z * inv + sk.z, 0.f);
    o.w = fmaxf(acc.w * inv + sk.w, 0.f);
    ((float4*)g_h)[(size_t)n * 32 + lane] = o;
}

// ---------------- layer-2 aggregation: warp per node, online softmax, H=1 D=64 ----------------
__global__ __launch_bounds__(256) void agg2_kernel(float* __restrict__ out, int Nn)
{
    int warp = (blockIdx.x * blockDim.x + threadIdx.x) >> 5;
    int lane = threadIdx.x & 31;
    if (warp >= Nn) return;
    int n = warp;

    const float2* Q2 = (const float2*)g_Q2;
    const float2* K2 = (const float2*)g_K2;
    const float2* V2 = (const float2*)g_V2;
    const float2* S2 = (const float2*)g_S2;

    float2 q = Q2[(size_t)n * 32 + lane];

    int beg = g_rowptr[n];
    int end = g_rowptr[n + 1];

    float m = -1e30f, s = 0.f;
    float2 acc = make_float2(0.f, 0.f);

    if (beg < end) {
        int src = g_psrc[beg];
        float2 kk = K2[(size_t)src * 32 + lane];
        float2 vv = V2[(size_t)src * 32 + lane];
        for (int e = beg; e < end; e++) {
            int nsrc = (e + 1 < end) ? g_psrc[e + 1] : src;
            float2 nk = K2[(size_t)nsrc * 32 + lane];
            float2 nv = V2[(size_t)nsrc * 32 + lane];

            float d = kk.x * q.x + kk.y * q.y;
            #pragma unroll
            for (int off = 16; off > 0; off >>= 1)
                d += __shfl_xor_sync(0xffffffffu, d, off);
            float sc = d * 0.125f;

            float mn = fmaxf(m, sc);
            float c  = __expf(m - mn);
            float p  = __expf(sc - mn);
            s = s * c + p;
            acc.x = acc.x * c + p * vv.x;
            acc.y = acc.y * c + p * vv.y;
            m = mn;

            kk = nk; vv = nv;
        }
    }

    float inv = 1.f / (s + 1e-16f);
    float2 sk = S2[(size_t)n * 32 + lane];
    float2 o;
    o.x = acc.x * inv + sk.x;
    o.y = acc.y * inv + sk.y;
    ((float2*)out)[(size_t)n * 32 + lane] = o;
}

// ---------------- launch ----------------
extern "C" void kernel_launch(void* const* d_in, const int* in_sizes, int n_in,
                              void* d_out, int out_size)
{
    const float* x   = (const float*)d_in[0];
    const float* Wq1 = (const float*)d_in[1];  const float* bq1 = (const float*)d_in[2];
    const float* Wk1 = (const float*)d_in[3];  const float* bk1 = (const float*)d_in[4];
    const float* Wv1 = (const float*)d_in[5];  const float* bv1 = (const float*)d_in[6];
    const float* Ws1 = (const float*)d_in[7];  const float* bs1 = (const float*)d_in[8];
    const float* Wq2 = (const float*)d_in[9];  const float* bq2 = (const float*)d_in[10];
    const float* Wk2 = (const float*)d_in[11]; const float* bk2 = (const float*)d_in[12];
    const float* Wv2 = (const float*)d_in[13]; const float* bv2 = (const float*)d_in[14];
    const float* Ws2 = (const float*)d_in[15]; const float* bs2 = (const float*)d_in[16];
    const int* esrc  = (const int*)d_in[17];
    const int* edst  = (const int*)d_in[18];
    float* out = (float*)d_out;

    int Nn = in_sizes[0] / 128;
    int E  = in_sizes[17];

    int rowBlocksAll = (Nn + 127) / 128;          // 391
    int halfBlocks   = (rowBlocksAll + 1) / 2;    // 196
    int H            = halfBlocks * 128;          // 25088 (<= Nn assumed; guard below)
    if (H > Nn) H = Nn;
    int rb2          = rowBlocksAll - halfBlocks; // 195

    // One-time side stream + events (created on the correctness call, which
    // precedes graph capture; reused identically on every call).
    static cudaStream_t s2 = nullptr;
    static cudaEvent_t evFork = nullptr, evCSR = nullptr, evQS1 = nullptr,
                       evQS2 = nullptr, evA1 = nullptr, evG2c1 = nullptr;
    if (s2 == nullptr) {
        cudaStreamCreateWithFlags(&s2, cudaStreamNonBlocking);
        cudaEventCreateWithFlags(&evFork, cudaEventDisableTiming);
        cudaEventCreateWithFlags(&evCSR,  cudaEventDisableTiming);
        cudaEventCreateWithFlags(&evQS1,  cudaEventDisableTiming);
        cudaEventCreateWithFlags(&evQS2,  cudaEventDisableTiming);
        cudaEventCreateWithFlags(&evA1,   cudaEventDisableTiming);
        cudaEventCreateWithFlags(&evG2c1, cudaEventDisableTiming);
    }

    // ---- fork: CSR build on s2 ----
    cudaEventRecord(evFork, 0);
    cudaStreamWaitEvent(s2, evFork, 0);
    k_zero<<<(Nn + 255) / 256, 256, 0, s2>>>(Nn);
    k_hist<<<(E + 255) / 256, 256, 0, s2>>>(edst, E);
    k_scan<<<1, 1024, 0, s2>>>(Nn);
    k_scatter<<<(E + 255) / 256, 256, 0, s2>>>(esrc, edst, E);
    cudaEventRecord(evCSR, s2);

    // ---- main: gemm1 K/V (all rows) then Q/S chunk1 ----
    dim3 gKV(2, rowBlocksAll, 2);
    gemm_tc<<<gKV, 256>>>(x, Wk1, Wv1, nullptr, nullptr, bk1, bv1, nullptr, nullptr,
                          Nn, 128, /*outBase=*/2, /*rowBeg=*/0);
    dim3 gQS1(2, halfBlocks, 2);
    gemm_tc<<<gQS1, 256>>>(x, Wq1, Ws1, nullptr, nullptr, bq1, bs1, nullptr, nullptr,
                           Nn, 128, /*outBase=*/0, /*rowBeg=*/0);
    cudaEventRecord(evQS1, 0);

    // ---- s2: gemm1 Q/S chunk2, overlapping agg1 chunk1 on main ----
    cudaStreamWaitEvent(s2, evQS1, 0);
    if (rb2 > 0) {
        dim3 gQS2(2, rb2, 2);
        gemm_tc<<<gQS2, 256, 0, s2>>>(x, Wq1, Ws1, nullptr, nullptr, bq1, bs1, nullptr, nullptr,
                                      Nn, 128, /*outBase=*/0, /*rowBeg=*/H);
    }
    cudaEventRecord(evQS2, s2);

    // ---- main: agg1 chunk1 (nodes [0,H)) ----
    cudaStreamWaitEvent(0, evCSR, 0);
    int a1c1Blocks = (H + 7) / 8;
    agg1_kernel<<<a1c1Blocks, 256>>>(0, H);
    cudaEventRecord(evA1, 0);

    // ---- s2: gemm2 chunk1 (rows [0,H)), overlapping agg1 chunk2 on main ----
    cudaStreamWaitEvent(s2, evA1, 0);
    dim3 g2c1(1, halfBlocks, 4);
    gemm_tc<<<g2c1, 256, 0, s2>>>(nullptr, Wq2, Wk2, Wv2, Ws2, bq2, bk2, bv2, bs2,
                                  Nn, 64, /*outBase=*/4, /*rowBeg=*/0);
    cudaEventRecord(evG2c1, s2);

    // ---- main: agg1 chunk2 (nodes [H,Nn)) ----
    cudaStreamWaitEvent(0, evQS2, 0);
    if (Nn > H) {
        int a1c2Blocks = (Nn - H + 7) / 8;
        agg1_kernel<<<a1c2Blocks, 256>>>(H, Nn);
    }

    // ---- main: gemm2 chunk2 (rows [H,..)) ----
    if (rb2 > 0) {
        dim3 g2c2(1, rb2, 4);
        gemm_tc<<<g2c2, 256>>>(nullptr, Wq2, Wk2, Wv2, Ws2, bq2, bk2, bv2, bs2,
                               Nn, 64, /*outBase=*/4, /*rowBeg=*/H);
    }

    // ---- main: agg2 (needs gemm2 chunk1 from s2 + chunk2 on main) ----
    cudaStreamWaitEvent(0, evG2c1, 0);
    int aggBlocks = (Nn + 7) / 8;
    agg2_kernel<<<aggBlocks, 256>>>(out, Nn);
}